// round 6
// baseline (speedup 1.0000x reference)
#include <cuda_runtime.h>
#include <cuda_fp16.h>
#include <cuda_bf16.h>
#include <cstdint>

#define NC  100000
#define NT  100000
#define NNZ 640000
#define D   128
#define CAP 32           // bucket capacity per row (avg 6.4 nnz/row, Poisson)

#define PREP_BLOCKS 625
#define PREP_T      256
#define PREP_STRIDE (PREP_BLOCKS * PREP_T)       // 160000
#define BUCKET_IT   (NNZ / PREP_STRIDE)          // 4 (exact)
#define CONV_UNITS  (NT * D / 8)                 // 1.6M units of 8 floats
#define CONV_IT     (CONV_UNITS / PREP_STRIDE)   // 10 (exact)

// ---- device-global scratch (no allocation allowed) ----
__device__ int   g_cnt[NC];            // per-row nnz count
__device__ int   g_bucket[NC * CAP];   // col indices bucketed by row (12.8 MB)
__device__ int   g_ovf_cnt;            // overflow entry count
__device__ int2  g_ovf[NNZ];           // overflow (row,col) pairs (worst case)
__device__ uint4 g_half[NT * D / 8];   // fp16 copy of mat (25.6 MB), 8 halves/uint4

// Phase 1 (fused): bucket the nonzeros AND convert mat fp32->fp16.
// Convert's coalesced streaming rides under the bucket atomics' latency.
__global__ __launch_bounds__(PREP_T) void prep_kernel(
    const int*    __restrict__ row,
    const int*    __restrict__ col,
    const float4* __restrict__ matf4) {
    const int tid = blockIdx.x * PREP_T + threadIdx.x;

    int r[BUCKET_IT], c[BUCKET_IT], slot[BUCKET_IT];
    #pragma unroll
    for (int k = 0; k < BUCKET_IT; ++k) {
        int i = tid + k * PREP_STRIDE;
        r[k] = __ldg(row + i);
        c[k] = __ldg(col + i);
    }
    #pragma unroll
    for (int k = 0; k < BUCKET_IT; ++k)
        slot[k] = atomicAdd(&g_cnt[r[k]], 1);

    // fp32 -> fp16: 8 floats (two float4) -> one uint4 of 8 halves.
    // Layout: g_half viewed as halves is exactly mat's row-major layout.
    #pragma unroll
    for (int j = 0; j < CONV_IT; ++j) {
        int p = tid + j * PREP_STRIDE;
        float4 a = __ldg(matf4 + 2 * p);
        float4 b = __ldg(matf4 + 2 * p + 1);
        __half2 h0 = __float22half2_rn(make_float2(a.x, a.y));
        __half2 h1 = __float22half2_rn(make_float2(a.z, a.w));
        __half2 h2 = __float22half2_rn(make_float2(b.x, b.y));
        __half2 h3 = __float22half2_rn(make_float2(b.z, b.w));
        uint4 u;
        u.x = *reinterpret_cast<unsigned*>(&h0);
        u.y = *reinterpret_cast<unsigned*>(&h1);
        u.z = *reinterpret_cast<unsigned*>(&h2);
        u.w = *reinterpret_cast<unsigned*>(&h3);
        g_half[p] = u;
    }

    #pragma unroll
    for (int k = 0; k < BUCKET_IT; ++k) {
        if (slot[k] < CAP) {
            g_bucket[r[k] * CAP + slot[k]] = c[k];
        } else {
            int p = atomicAdd(&g_ovf_cnt, 1);
            g_ovf[p] = make_int2(r[k], c[k]);
        }
    }
}

// Phase 2: one warp per output row over the fp16 copy. One fp16 row is
// 128 halves = 256 B = 32 lanes x uint2 (4 halves each). Lane l preloads
// bucket col l; shfl broadcast; 4x fp32 accumulation; one float4 store.
__global__ __launch_bounds__(256) void gather_sum_kernel(
    float4* __restrict__ out) {
    int r    = (blockIdx.x * blockDim.x + threadIdx.x) >> 5;
    int lane = threadIdx.x & 31;
    if (r >= NC) return;

    int n = __ldg(g_cnt + r);
    if (n > CAP) n = CAP;

    int cj = (lane < n) ? __ldg(g_bucket + r * CAP + lane) : 0;

    const uint2* halfrows = reinterpret_cast<const uint2*>(g_half);

    float ax = 0.f, ay = 0.f, az = 0.f, aw = 0.f;
    #pragma unroll 8
    for (int j = 0; j < n; ++j) {
        int c = __shfl_sync(0xffffffffu, cj, j);
        uint2 h = __ldg(halfrows + (size_t)c * 32 + lane);
        __half2 p0 = *reinterpret_cast<__half2*>(&h.x);
        __half2 p1 = *reinterpret_cast<__half2*>(&h.y);
        float2 f0 = __half22float2(p0);
        float2 f1 = __half22float2(p1);
        ax += f0.x; ay += f0.y; az += f1.x; aw += f1.y;
    }

    out[(size_t)r * 32 + lane] = make_float4(ax, ay, az, aw);
}

// Phase 3: apply overflow entries (expected count: 0). Lane owns 4 floats.
__global__ __launch_bounds__(256) void overflow_kernel(float* __restrict__ out) {
    int warp  = (blockIdx.x * blockDim.x + threadIdx.x) >> 5;
    int lane  = threadIdx.x & 31;
    int nwarp = (gridDim.x * blockDim.x) >> 5;
    int cnt   = g_ovf_cnt;
    if (cnt > NNZ) cnt = NNZ;
    const uint2* halfrows = reinterpret_cast<const uint2*>(g_half);
    for (int i = warp; i < cnt; i += nwarp) {
        int2 e = g_ovf[i];
        uint2 h = __ldg(halfrows + (size_t)e.y * 32 + lane);
        __half2 p0 = *reinterpret_cast<__half2*>(&h.x);
        __half2 p1 = *reinterpret_cast<__half2*>(&h.y);
        float2 f0 = __half22float2(p0);
        float2 f1 = __half22float2(p1);
        float* dst = out + (size_t)e.x * D + lane * 4;
        asm volatile("red.global.add.v4.f32 [%0], {%1, %2, %3, %4};"
                     :: "l"(dst), "f"(f0.x), "f"(f0.y), "f"(f1.x), "f"(f1.y)
                     : "memory");
    }
}

extern "C" void kernel_launch(void* const* d_in, const int* in_sizes, int n_in,
                              void* d_out, int out_size) {
    const float4* mat = (const float4*)d_in[0];
    const int*    row = (const int*)d_in[1];
    const int*    col = (const int*)d_in[2];
    float4*       out = (float4*)d_out;

    void* cnt_ptr = nullptr;
    void* ovf_ptr = nullptr;
    cudaGetSymbolAddress(&cnt_ptr, g_cnt);
    cudaGetSymbolAddress(&ovf_ptr, g_ovf_cnt);
    cudaMemsetAsync(cnt_ptr, 0, (size_t)NC * sizeof(int));
    cudaMemsetAsync(ovf_ptr, 0, sizeof(int));

    prep_kernel<<<PREP_BLOCKS, PREP_T>>>(row, col, mat);

    const long long total_threads = (long long)NC * 32;
    gather_sum_kernel<<<(int)((total_threads + 255) / 256), 256>>>(out);

    overflow_kernel<<<16, 256>>>((float*)d_out);
}

// round 7
// speedup vs baseline: 1.2054x; 1.2054x over previous
#include <cuda_runtime.h>
#include <cuda_fp16.h>
#include <cuda_bf16.h>
#include <cstdint>

#define NC  100000
#define NT  100000
#define NNZ 640000
#define D   128
#define CAP 32           // bucket capacity per row (Poisson mean 6.4)

#define PREP_PAIRS  518                     // grid = 1036 blocks (~1 wave)
#define PREP_T      256
#define PREP_HALF   (PREP_PAIRS * PREP_T)   // threads per role
#define CONV_UNITS  (NT * D / 8)            // 1.6M uint4 units (8 halves each)

// ---- device-global scratch (no allocation allowed) ----
__device__ int   g_cnt[NC];            // per-row nnz count
__device__ int   g_bucket[NC * CAP];   // col indices bucketed by row (12.8 MB)
__device__ int   g_ovf_cnt;            // overflow entry count
__device__ int2  g_ovf[NNZ];           // overflow (row,col) pairs (worst case)
__device__ uint4 g_half[NT * D / 8];   // fp16 copy of mat (25.6 MB)

// Phase 1: block-role specialized. Even blocks stream-convert mat fp32->fp16
// (DRAM-bound); odd blocks bucket the nonzeros (L2-atomic-latency-bound).
// The two roles use disjoint resources and overlap across SMs instead of
// serializing inside one thread (R6's mistake).
__global__ __launch_bounds__(PREP_T) void prep_kernel(
    const int*    __restrict__ row,
    const int*    __restrict__ col,
    const float4* __restrict__ matf4) {
    const int pair = blockIdx.x >> 1;
    const int tid  = pair * PREP_T + threadIdx.x;

    if ((blockIdx.x & 1) == 0) {
        // ---- convert role: coalesced streaming, grid-stride ----
        for (int p = tid; p < CONV_UNITS; p += PREP_HALF) {
            float4 a = __ldg(matf4 + 2 * p);
            float4 b = __ldg(matf4 + 2 * p + 1);
            __half2 h0 = __float22half2_rn(make_float2(a.x, a.y));
            __half2 h1 = __float22half2_rn(make_float2(a.z, a.w));
            __half2 h2 = __float22half2_rn(make_float2(b.x, b.y));
            __half2 h3 = __float22half2_rn(make_float2(b.z, b.w));
            uint4 u;
            u.x = *reinterpret_cast<unsigned*>(&h0);
            u.y = *reinterpret_cast<unsigned*>(&h1);
            u.z = *reinterpret_cast<unsigned*>(&h2);
            u.w = *reinterpret_cast<unsigned*>(&h3);
            g_half[p] = u;
        }
    } else {
        // ---- bucket role: grid-stride over nonzeros ----
        for (int i = tid; i < NNZ; i += PREP_HALF) {
            int r = __ldg(row + i);
            int c = __ldg(col + i);
            int slot = atomicAdd(&g_cnt[r], 1);
            if (slot < CAP) {
                g_bucket[r * CAP + slot] = c;
            } else {
                int p = atomicAdd(&g_ovf_cnt, 1);
                g_ovf[p] = make_int2(r, c);
            }
        }
    }
}

// Phase 2: one warp per output row. fp16 row = 256 B = 32 lanes x uint2.
// All 32 bucket slots are loaded unconditionally (one 128B line, independent
// of the cnt load -> two parallel chains). The first 8 contributions are a
// fully-unrolled PREDICATED load batch (8 independent LDGs in flight), then
// separate accumulation; rows with n>8 (~20%) take a scalar tail.
__global__ __launch_bounds__(256) void gather_sum_kernel(
    float4* __restrict__ out) {
    int r    = (blockIdx.x * blockDim.x + threadIdx.x) >> 5;
    int lane = threadIdx.x & 31;
    if (r >= NC) return;

    const uint2* halfrows = reinterpret_cast<const uint2*>(g_half);

    // Two independent loads issued back-to-back.
    int cj = __ldg(g_bucket + r * CAP + lane);   // slot 'lane' (may be stale; predicated use)
    int n  = __ldg(g_cnt + r);
    if (n > CAP) n = CAP;

    float ax = 0.f, ay = 0.f, az = 0.f, aw = 0.f;

    uint2 v[8];
    #pragma unroll
    for (int j = 0; j < 8; ++j) {
        int c = __shfl_sync(0xffffffffu, cj, j);
        if (j < n) v[j] = __ldg(halfrows + (size_t)c * 32 + lane);
    }
    #pragma unroll
    for (int j = 0; j < 8; ++j) {
        if (j < n) {
            float2 f0 = __half22float2(*reinterpret_cast<__half2*>(&v[j].x));
            float2 f1 = __half22float2(*reinterpret_cast<__half2*>(&v[j].y));
            ax += f0.x; ay += f0.y; az += f1.x; aw += f1.y;
        }
    }
    // Rare tail: n in (8, 32].
    for (int j = 8; j < n; ++j) {
        int c = __shfl_sync(0xffffffffu, cj, j);
        uint2 h = __ldg(halfrows + (size_t)c * 32 + lane);
        float2 f0 = __half22float2(*reinterpret_cast<__half2*>(&h.x));
        float2 f1 = __half22float2(*reinterpret_cast<__half2*>(&h.y));
        ax += f0.x; ay += f0.y; az += f1.x; aw += f1.y;
    }

    out[(size_t)r * 32 + lane] = make_float4(ax, ay, az, aw);
}

// Phase 3: apply overflow entries (expected count: 0). Lane owns 4 floats.
__global__ __launch_bounds__(256) void overflow_kernel(float* __restrict__ out) {
    int warp  = (blockIdx.x * blockDim.x + threadIdx.x) >> 5;
    int lane  = threadIdx.x & 31;
    int nwarp = (gridDim.x * blockDim.x) >> 5;
    int cnt   = g_ovf_cnt;
    if (cnt > NNZ) cnt = NNZ;
    const uint2* halfrows = reinterpret_cast<const uint2*>(g_half);
    for (int i = warp; i < cnt; i += nwarp) {
        int2 e = g_ovf[i];
        uint2 h = __ldg(halfrows + (size_t)e.y * 32 + lane);
        float2 f0 = __half22float2(*reinterpret_cast<__half2*>(&h.x));
        float2 f1 = __half22float2(*reinterpret_cast<__half2*>(&h.y));
        float* dst = out + (size_t)e.x * D + lane * 4;
        asm volatile("red.global.add.v4.f32 [%0], {%1, %2, %3, %4};"
                     :: "l"(dst), "f"(f0.x), "f"(f0.y), "f"(f1.x), "f"(f1.y)
                     : "memory");
    }
}

extern "C" void kernel_launch(void* const* d_in, const int* in_sizes, int n_in,
                              void* d_out, int out_size) {
    const float4* mat = (const float4*)d_in[0];
    const int*    row = (const int*)d_in[1];
    const int*    col = (const int*)d_in[2];
    float4*       out = (float4*)d_out;

    void* cnt_ptr = nullptr;
    void* ovf_ptr = nullptr;
    cudaGetSymbolAddress(&cnt_ptr, g_cnt);
    cudaGetSymbolAddress(&ovf_ptr, g_ovf_cnt);
    cudaMemsetAsync(cnt_ptr, 0, (size_t)NC * sizeof(int));
    cudaMemsetAsync(ovf_ptr, 0, sizeof(int));

    prep_kernel<<<PREP_PAIRS * 2, PREP_T>>>(row, col, mat);

    const long long total_threads = (long long)NC * 32;
    gather_sum_kernel<<<(int)((total_threads + 255) / 256), 256>>>(out);

    overflow_kernel<<<16, 256>>>((float*)d_out);
}